// round 6
// baseline (speedup 1.0000x reference)
#include <cuda_runtime.h>
#include <cuda_bf16.h>
#include <cuda_fp16.h>
#include <cstdint>

#define NB2 64   // persistent blocks in recurrent kernel

// ------------------------------------------------------------------
// Device-global scratch (allocation-free)
// ------------------------------------------------------------------
__device__ float  d_Gx[(size_t)16384 * 4096];      // x@Wx + bias
__device__ float  d_H2[(size_t)16384 * 1024];      // h [b*512+t][j] for final FC
__device__ __half d_Hts[(size_t)513 * 32 * 1024];  // h fp16 [t][b][k_perm]
__device__ __half d_xh[(size_t)16384 * 512];       // x converted to fp16
__device__ __half d_Wxh[(size_t)512 * 4096];       // packed fp16 input weights, k-pair interleaved
__device__ float  d_bx[4096];                      // packed gate biases
__device__ unsigned d_cnt[512];                    // per-step grid-barrier counters

// ------------------------------------------------------------------
// Helpers
// ------------------------------------------------------------------
__device__ __forceinline__ unsigned cvt_tf32(float x) {
    unsigned u;
    asm("cvt.rna.tf32.f32 %0, %1;" : "=r"(u) : "f"(x));
    return u;
}

__device__ __forceinline__ void mma_tf32(float c[4],
                                         unsigned a0, unsigned a1, unsigned a2, unsigned a3,
                                         unsigned b0, unsigned b1) {
    asm volatile(
        "mma.sync.aligned.m16n8k8.row.col.f32.tf32.tf32.f32 "
        "{%0,%1,%2,%3},{%4,%5,%6,%7},{%8,%9},{%0,%1,%2,%3};"
        : "+f"(c[0]), "+f"(c[1]), "+f"(c[2]), "+f"(c[3])
        : "r"(a0), "r"(a1), "r"(a2), "r"(a3), "r"(b0), "r"(b1));
}

__device__ __forceinline__ void mma_f16(float c[4],
                                        unsigned a0, unsigned a1, unsigned a2, unsigned a3,
                                        unsigned b0, unsigned b1) {
    asm volatile(
        "mma.sync.aligned.m16n8k16.row.col.f32.f16.f16.f32 "
        "{%0,%1,%2,%3},{%4,%5,%6,%7},{%8,%9},{%0,%1,%2,%3};"
        : "+f"(c[0]), "+f"(c[1]), "+f"(c[2]), "+f"(c[3])
        : "r"(a0), "r"(a1), "r"(a2), "r"(a3), "r"(b0), "r"(b1));
}

__device__ __forceinline__ float sigm(float x) { return 1.f / (1.f + __expf(-x)); }

// k-permutation of the fp16 h layout (same as R5; verified numerically)
__device__ __forceinline__ int perm32(int j) {
    int tig = (j & 7) >> 1;
    int a   = (j & 31) >> 4;
    return (j & ~31) + tig * 8 + a * 4 + (j & 1) + 2 * ((j & 15) >> 3);
}

// ------------------------------------------------------------------
// Init: zero h_0 slab and barrier counters (runs every launch/replay)
// ------------------------------------------------------------------
__global__ void init_kernel() {
    int idx = blockIdx.x * blockDim.x + threadIdx.x;
    if (idx < 16384) ((unsigned*)d_Hts)[idx] = 0u;   // 32768 halves
    if (idx < 512) d_cnt[idx] = 0u;
}

// ------------------------------------------------------------------
// Convert x to fp16 (2 floats / thread)
// ------------------------------------------------------------------
__global__ void xconv_kernel(const float* __restrict__ x) {
    int idx = blockIdx.x * blockDim.x + threadIdx.x;   // 0 .. 4194303
    float2 v = *(const float2*)(x + 2 * (size_t)idx);
    ((__half2*)d_xh)[idx] = __floats2half2_rn(v.x, v.y);
}

// ------------------------------------------------------------------
// Pack fp16 weights (k-pair interleaved: elem (k,n) at ((k>>1)*4096+n)*2+(k&1))
// and the gate biases.
// ------------------------------------------------------------------
__global__ void pack_kernel(const float* __restrict__ Wf, const float* __restrict__ Wi,
                            const float* __restrict__ Wg, const float* __restrict__ Wo,
                            const float* __restrict__ bf, const float* __restrict__ bi,
                            const float* __restrict__ bg, const float* __restrict__ bo) {
    int idx = blockIdx.x * blockDim.x + threadIdx.x;
    if (idx < 512 * 1024) {
        int k = idx >> 10, j = idx & 1023;
        size_t base = ((size_t)(k >> 1) * 4096) * 2 + (k & 1);
        d_Wxh[base + (size_t)(j) * 2]        = __float2half_rn(Wf[idx]);
        d_Wxh[base + (size_t)(j + 1024) * 2] = __float2half_rn(Wi[idx]);
        d_Wxh[base + (size_t)(j + 2048) * 2] = __float2half_rn(Wg[idx]);
        d_Wxh[base + (size_t)(j + 3072) * 2] = __float2half_rn(Wo[idx]);
    }
    if (idx < 1024) {
        d_bx[idx]        = bf[idx];
        d_bx[idx + 1024] = bi[idx];
        d_bx[idx + 2048] = bg[idx];
        d_bx[idx + 3072] = bo[idx];
    }
}

// ------------------------------------------------------------------
// Phase-1 fp16 GEMM (specialized): d_Gx = d_xh @ d_Wxh + d_bx
// M=16384, N=4096, K=512. 128x128x32 tiles, 8 warps (warp 64x32).
// ------------------------------------------------------------------
__global__ void __launch_bounds__(256) gemm_f16_gx() {
    __shared__ __half sAh[128 * 40];   // 128 rows x 32 halves (+8 pad)
    __shared__ __half sBh[16 * 272];   // 16 k2-rows x 128 cols x 2 (+16 pad)

    const int tid = threadIdx.x;
    const int w = tid >> 5, lane = tid & 31;
    const int g = lane >> 2, tig = lane & 3;
    const int wm = (w >> 2) * 64, wn = (w & 3) * 32;
    const int m0 = blockIdx.y * 128, n0 = blockIdx.x * 128;

    float Cr[4][4][4];
#pragma unroll
    for (int a = 0; a < 4; a++)
#pragma unroll
        for (int b = 0; b < 4; b++)
#pragma unroll
            for (int c = 0; c < 4; c++) Cr[a][b][c] = 0.f;

    for (int kc = 0; kc < 16; kc++) {
        const int k0 = kc * 32;
        __syncthreads();
        // A slab: 128 rows x 32 halves = 512 x 16B chunks
#pragma unroll
        for (int i = 0; i < 2; i++) {
            int lin = tid + i * 256;
            int r = lin >> 2, q = lin & 3;
            *(uint4*)(sAh + r * 40 + q * 8) =
                *(const uint4*)(d_xh + (size_t)(m0 + r) * 512 + k0 + q * 8);
        }
        // B slab: 16 k2-rows x 128 cols x 2 halves = 512 x 16B chunks
#pragma unroll
        for (int i = 0; i < 2; i++) {
            int lin = tid + i * 256;
            int k2r = lin >> 5, c4 = lin & 31;
            *(uint4*)(sBh + k2r * 272 + c4 * 8) =
                *(const uint4*)(d_Wxh + ((size_t)((k0 >> 1) + k2r) * 4096 + n0 + c4 * 4) * 2);
        }
        __syncthreads();

#pragma unroll
        for (int kt = 0; kt < 2; kt++) {
            unsigned bf_[4][2];
#pragma unroll
            for (int nt = 0; nt < 4; nt++) {
                int jc = wn + nt * 8 + g;
                bf_[nt][0] = *(const unsigned*)(sBh + (kt * 8 + tig) * 272 + jc * 2);
                bf_[nt][1] = *(const unsigned*)(sBh + (kt * 8 + tig + 4) * 272 + jc * 2);
            }
#pragma unroll
            for (int mt = 0; mt < 4; mt++) {
                int ro = (wm + mt * 16 + g) * 40 + kt * 16 + 2 * tig;
                unsigned a0 = *(const unsigned*)(sAh + ro);
                unsigned a1 = *(const unsigned*)(sAh + ro + 8 * 40);
                unsigned a2 = *(const unsigned*)(sAh + ro + 8);
                unsigned a3 = *(const unsigned*)(sAh + ro + 8 * 40 + 8);
#pragma unroll
                for (int nt = 0; nt < 4; nt++)
                    mma_f16(Cr[mt][nt], a0, a1, a2, a3, bf_[nt][0], bf_[nt][1]);
            }
        }
    }

    // Epilogue: bias + store fp32 Gx
#pragma unroll
    for (int mt = 0; mt < 4; mt++) {
#pragma unroll
        for (int nt = 0; nt < 4; nt++) {
            int row = m0 + wm + mt * 16 + g;
            int col = n0 + wn + nt * 8 + 2 * tig;
            float bx = d_bx[col], by = d_bx[col + 1];
            float2 v0 = make_float2(Cr[mt][nt][0] + bx, Cr[mt][nt][1] + by);
            float2 v1 = make_float2(Cr[mt][nt][2] + bx, Cr[mt][nt][3] + by);
            *(float2*)(d_Gx + (size_t)row * 4096 + col) = v0;
            *(float2*)(d_Gx + (size_t)(row + 8) * 4096 + col) = v1;
        }
    }
}

// ------------------------------------------------------------------
// tf32 GEMM (phase 3): C[M,N] = A[M,K] @ B[K,N] + bias[N]
// ------------------------------------------------------------------
__global__ void __launch_bounds__(256) gemm_tf32_bias(
    const float* __restrict__ A, const float* __restrict__ Bm,
    const float* __restrict__ bias, float* __restrict__ C,
    int M, int N, int K) {
    __shared__ float sA[128 * 20];
    __shared__ float sB[16 * 132];

    const int tid = threadIdx.x;
    const int w = tid >> 5, lane = tid & 31;
    const int g = lane >> 2, tig = lane & 3;
    const int wm = (w >> 2) * 64, wn = (w & 3) * 32;
    const int m0 = blockIdx.y * 128, n0 = blockIdx.x * 128;

    float Cr[4][4][4];
#pragma unroll
    for (int a = 0; a < 4; a++)
#pragma unroll
        for (int b = 0; b < 4; b++)
#pragma unroll
            for (int c = 0; c < 4; c++) Cr[a][b][c] = 0.f;

    const int nk = K / 16;
    for (int kc = 0; kc < nk; kc++) {
        const int k0 = kc * 16;
        __syncthreads();
#pragma unroll
        for (int i = 0; i < 2; i++) {
            int lin = tid + i * 256;
            int r = lin >> 2, q = lin & 3;
            float4 v = *(const float4*)(A + (size_t)(m0 + r) * K + k0 + q * 4);
            *(float4*)(sA + r * 20 + q * 4) = v;
        }
#pragma unroll
        for (int i = 0; i < 2; i++) {
            int lin = tid + i * 256;
            int r = lin >> 5, q = lin & 31;
            float4 v = *(const float4*)(Bm + (size_t)(k0 + r) * N + n0 + q * 4);
            *(float4*)(sB + r * 132 + q * 4) = v;
        }
        __syncthreads();

#pragma unroll
        for (int k8 = 0; k8 < 2; k8++) {
            unsigned bf_[4][2];
#pragma unroll
            for (int nt = 0; nt < 4; nt++) {
                bf_[nt][0] = cvt_tf32(sB[(k8 * 8 + tig) * 132 + wn + nt * 8 + g]);
                bf_[nt][1] = cvt_tf32(sB[(k8 * 8 + tig + 4) * 132 + wn + nt * 8 + g]);
            }
#pragma unroll
            for (int mt = 0; mt < 4; mt++) {
                const float* ap = sA + (wm + mt * 16 + g) * 20 + k8 * 8 + tig;
                unsigned a0 = cvt_tf32(ap[0]);
                unsigned a1 = cvt_tf32(ap[8 * 20]);
                unsigned a2 = cvt_tf32(ap[4]);
                unsigned a3 = cvt_tf32(ap[8 * 20 + 4]);
#pragma unroll
                for (int nt = 0; nt < 4; nt++)
                    mma_tf32(Cr[mt][nt], a0, a1, a2, a3, bf_[nt][0], bf_[nt][1]);
            }
        }
    }

#pragma unroll
    for (int mt = 0; mt < 4; mt++) {
#pragma unroll
        for (int nt = 0; nt < 4; nt++) {
            int row = m0 + wm + mt * 16 + g;
            int col = n0 + wn + nt * 8 + 2 * tig;
            float bx = bias[col], by = bias[col + 1];
            float2 v0 = make_float2(Cr[mt][nt][0] + bx, Cr[mt][nt][1] + by);
            float2 v1 = make_float2(Cr[mt][nt][2] + bx, Cr[mt][nt][3] + by);
            *(float2*)(C + (size_t)row * N + col) = v0;
            *(float2*)(C + (size_t)(row + 8) * N + col) = v1;
        }
    }
}

// ------------------------------------------------------------------
// Persistent recurrent kernel. 64 blocks x 512 threads (16 warps).
// Block bk owns hidden units [bk*16, bk*16+16) x 4 gates (64 cols).
// Warp w: col-group cg=w>>3 (8 units), K-slice ks=w&7 (K=128).
// Weights: fp16 B-fragments in regs (Wr[8][4][2] = 64 regs).
// h fp16 [t][b][k_perm]; per 32-k group one LDG.128/lane = A frags
// for two k16 tiles. Reduction: 8 regions per col-group.
// Fence-free acq_rel grid barrier over 64 blocks.
// ------------------------------------------------------------------
__global__ void __launch_bounds__(512) lstm_rec(
    const float* __restrict__ Wf, const float* __restrict__ Wi,
    const float* __restrict__ Wg, const float* __restrict__ Wo) {
    extern __shared__ float sPart[];   // 16 regions x 32 rows x 36 floats

    const int tid = threadIdx.x;
    const int w = tid >> 5, lane = tid & 31;
    const int g = lane >> 2, tig = lane & 3;
    const int cg = w >> 3, ks = w & 7;
    const int kw = ks * 128;
    const int bk = blockIdx.x;
    const int jb = bk * 16 + cg * 8;   // this warp's gate-col unit base

    // ---- Preload weights as fp16x2 B-fragments (true k order) ----
    const float* Wp[4] = {Wf, Wi, Wg, Wo};
    unsigned Wr[8][4][2];
#pragma unroll
    for (int kt = 0; kt < 8; kt++) {
#pragma unroll
        for (int nt = 0; nt < 4; nt++) {
            const float* ws = Wp[nt] + (size_t)(512 + kw + kt * 16 + 2 * tig) * 1024 + jb + g;
            __half2 lo = __floats2half2_rn(__ldg(ws), __ldg(ws + 1024));
            __half2 hi = __floats2half2_rn(__ldg(ws + 8 * 1024), __ldg(ws + 9 * 1024));
            Wr[kt][nt][0] = *(unsigned*)&lo;
            Wr[kt][nt][1] = *(unsigned*)&hi;
        }
    }

    // State-thread mapping: all 512 threads. b = tid/16, uu = tid%16
    const int b_ = tid >> 4, uu = tid & 15;
    float creg = 0.f;
    const int j = bk * 16 + uu;
    const int ppos = perm32(j);
    const int cgu = uu >> 3, u8 = uu & 7;

    // Incremented pointers
    const __half* hrd = d_Hts + kw + tig * 8;                           // += 32768
    __half* hwr = d_Hts + 32768 + (size_t)b_ * 1024 + ppos;             // += 32768
    const float* gxp = d_Gx + (size_t)(b_ * 512) * 4096 + bk * 16 + uu; // += 4096
    float* h2p = d_H2 + (size_t)(b_ * 512) * 1024 + bk * 16 + uu;       // += 1024
    unsigned* cntp = d_cnt;                                              // += 1

    for (int t = 0; t < 512; t++) {
        // Prefetch this step's input-projection gate values
        float gx0 = __ldcs(gxp);
        float gx1 = __ldcs(gxp + 1024);
        float gx2 = __ldcs(gxp + 2048);
        float gx3 = __ldcs(gxp + 3072);

        // ---- h_t @ Wh_slice (K=128 per warp, fp16 HMMA, fp32 accum) ----
        float Cr[2][4][4];
#pragma unroll
        for (int mt = 0; mt < 2; mt++)
#pragma unroll
            for (int nt = 0; nt < 4; nt++)
#pragma unroll
                for (int c = 0; c < 4; c++) Cr[mt][nt][c] = 0.f;

#pragma unroll
        for (int kb = 0; kb < 4; kb++) {
            const __half* base = hrd + kb * 32;
            uint4 V[2][2];
#pragma unroll
            for (int mt = 0; mt < 2; mt++) {
                V[mt][0] = __ldcg((const uint4*)(base + (mt * 16 + g) * 1024));
                V[mt][1] = __ldcg((const uint4*)(base + (mt * 16 + g + 8) * 1024));
            }
#pragma unroll
            for (int mt = 0; mt < 2; mt++) {
                const uint4& v0 = V[mt][0];
                const uint4& v1 = V[mt][1];
#pragma unroll
                for (int nt = 0; nt < 4; nt++)
                    mma_f16(Cr[mt][nt], v0.x, v1.x, v0.y, v1.y,
                            Wr[2 * kb][nt][0], Wr[2 * kb][nt][1]);
#pragma unroll
                for (int nt = 0; nt < 4; nt++)
                    mma_f16(Cr[mt][nt], v0.z, v1.z, v0.w, v1.w,
                            Wr[2 * kb + 1][nt][0], Wr[2 * kb + 1][nt][1]);
            }
        }

        // ---- Write partials: region w, gate-contiguous ----
        {
            float* sp = sPart + w * 1152;
#pragma unroll
            for (int mt = 0; mt < 2; mt++) {
#pragma unroll
                for (int nt = 0; nt < 4; nt++) {
                    int row = mt * 16 + g, c = 2 * tig;
                    sp[row * 36 + c * 4 + nt]             = Cr[mt][nt][0];
                    sp[row * 36 + (c + 1) * 4 + nt]       = Cr[mt][nt][1];
                    sp[(row + 8) * 36 + c * 4 + nt]       = Cr[mt][nt][2];
                    sp[(row + 8) * 36 + (c + 1) * 4 + nt] = Cr[mt][nt][3];
                }
            }
        }
        __syncthreads();

        // ---- Final reduce (8 x LDS.128) + gates + state update ----
        {
            const float4* rp = (const float4*)sPart + (size_t)cgu * 8 * 288 + b_ * 9 + u8;
            float4 s0 = rp[0], s1 = rp[288];
#pragma unroll
            for (int r = 2; r < 8; r += 2) {
                float4 a = rp[r * 288], b = rp[(r + 1) * 288];
                s0.x += a.x; s0.y += a.y; s0.z += a.z; s0.w += a.w;
                s1.x += b.x; s1.y += b.y; s1.z += b.z; s1.w += b.w;
            }
            float F = s0.x + s1.x + gx0;
            float I = s0.y + s1.y + gx1;
            float G = s0.z + s1.z + gx2;
            float O = s0.w + s1.w + gx3;
            creg = sigm(F) * creg + sigm(I) * tanhf(G);
            float h = sigm(O) * tanhf(creg);

            *hwr = __float2half_rn(h);
            *h2p = h;
        }
        __syncthreads();   // h stores issued + sPart reads done

        // ---- Fence-free grid barrier (acq_rel atomic + acquire poll) ----
        if (tid == 0) {
            unsigned ret;
            asm volatile("atom.acq_rel.gpu.add.u32 %0, [%1], %2;"
                         : "=r"(ret) : "l"(cntp), "r"(1u) : "memory");
            if (ret + 1u < NB2) {
                unsigned v;
                do {
                    asm volatile("ld.acquire.gpu.u32 %0, [%1];"
                                 : "=r"(v) : "l"(cntp) : "memory");
                } while (v < NB2);
            }
        }
        __syncthreads();

        hrd += 32768; hwr += 32768; gxp += 4096; h2p += 1024; cntp += 1;
    }
}

// ------------------------------------------------------------------
// Launch sequence (graph-capturable: kernel launches only)
// ------------------------------------------------------------------
extern "C" void kernel_launch(void* const* d_in, const int* in_sizes, int n_in,
                              void* d_out, int out_size) {
    const float* x    = (const float*)d_in[0];
    const float* W_f  = (const float*)d_in[1];
    const float* b_f  = (const float*)d_in[2];
    const float* W_i  = (const float*)d_in[3];
    const float* b_i  = (const float*)d_in[4];
    const float* W_g  = (const float*)d_in[5];
    const float* b_g  = (const float*)d_in[6];
    const float* W_o  = (const float*)d_in[7];
    const float* b_o  = (const float*)d_in[8];
    const float* W_fc = (const float*)d_in[9];
    const float* b_fc = (const float*)d_in[10];
    float* out = (float*)d_out;

    void *pH2;
    cudaGetSymbolAddress(&pH2, d_H2);

    static bool attr_set = false;
    if (!attr_set) {
        cudaFuncSetAttribute(lstm_rec, cudaFuncAttributeMaxDynamicSharedMemorySize,
                             16 * 1152 * 4);
        attr_set = true;
    }

    init_kernel<<<128, 256>>>();
    xconv_kernel<<<16384, 256>>>(x);
    pack_kernel<<<2048, 256>>>(W_f, W_i, W_g, W_o, b_f, b_i, b_g, b_o);

    // Phase 1: Gx = x @ Wx + bx   (fp16 HMMA, M=16384, N=4096, K=512)
    gemm_f16_gx<<<dim3(32, 128), 256>>>();

    // Phase 2: recurrence (persistent, 64 blocks)
    lstm_rec<<<NB2, 512, 16 * 1152 * 4>>>(W_f, W_i, W_g, W_o);

    // Phase 3: out = H2 @ W_fc + b_fc   (M=16384, N=512, K=1024)
    gemm_tf32_bias<<<dim3(4, 128), 256>>>(
        (const float*)pH2, W_fc, b_fc, out, 16384, 512, 1024);
}

// round 7
// speedup vs baseline: 1.2305x; 1.2305x over previous
#include <cuda_runtime.h>
#include <cuda_bf16.h>
#include <cuda_fp16.h>
#include <cstdint>

#define NB2 128   // persistent blocks in recurrent kernel (best measured)

// ------------------------------------------------------------------
// Device-global scratch (allocation-free)
// ------------------------------------------------------------------
__device__ float  d_Gx[(size_t)16384 * 4096];      // x@Wx + bias
__device__ __half d_H2h[(size_t)16384 * 1024];     // h fp16 [b*512+t][j] for final FC
__device__ __half d_Hts[(size_t)513 * 32 * 1024];  // h fp16 [t][b][k_perm]
__device__ __half d_xh[(size_t)16384 * 512];       // x converted to fp16
__device__ __half d_Wxh[(size_t)512 * 4096];       // fp16 input weights, k-pair interleaved
__device__ __half d_Wfch[(size_t)1024 * 512];      // fp16 W_fc, k-pair interleaved
__device__ float  d_bx[4096];                      // packed gate biases
__device__ unsigned d_cnt[512];                    // per-step grid-barrier counters

// ------------------------------------------------------------------
// Helpers
// ------------------------------------------------------------------
__device__ __forceinline__ void mma_f16(float c[4],
                                        unsigned a0, unsigned a1, unsigned a2, unsigned a3,
                                        unsigned b0, unsigned b1) {
    asm volatile(
        "mma.sync.aligned.m16n8k16.row.col.f32.f16.f16.f32 "
        "{%0,%1,%2,%3},{%4,%5,%6,%7},{%8,%9},{%0,%1,%2,%3};"
        : "+f"(c[0]), "+f"(c[1]), "+f"(c[2]), "+f"(c[3])
        : "r"(a0), "r"(a1), "r"(a2), "r"(a3), "r"(b0), "r"(b1));
}

__device__ __forceinline__ float sigm(float x) { return 1.f / (1.f + __expf(-x)); }

// k-permutation of the fp16 h layout (verified in R5/R6)
__device__ __forceinline__ int perm32(int j) {
    int tig = (j & 7) >> 1;
    int a   = (j & 31) >> 4;
    return (j & ~31) + tig * 8 + a * 4 + (j & 1) + 2 * ((j & 15) >> 3);
}

// ------------------------------------------------------------------
// Init: zero h_0 slab and barrier counters (runs every launch/replay)
// ------------------------------------------------------------------
__global__ void init_kernel() {
    int idx = blockIdx.x * blockDim.x + threadIdx.x;
    if (idx < 16384) ((unsigned*)d_Hts)[idx] = 0u;   // 32768 halves
    if (idx < 512) d_cnt[idx] = 0u;
}

// ------------------------------------------------------------------
// Convert x to fp16 (2 floats / thread)
// ------------------------------------------------------------------
__global__ void xconv_kernel(const float* __restrict__ x) {
    int idx = blockIdx.x * blockDim.x + threadIdx.x;
    float2 v = *(const float2*)(x + 2 * (size_t)idx);
    ((__half2*)d_xh)[idx] = __floats2half2_rn(v.x, v.y);
}

// ------------------------------------------------------------------
// Pack fp16 Wx (k-pair interleaved, N=4096) + gate biases
// ------------------------------------------------------------------
__global__ void pack_kernel(const float* __restrict__ Wf, const float* __restrict__ Wi,
                            const float* __restrict__ Wg, const float* __restrict__ Wo,
                            const float* __restrict__ bf, const float* __restrict__ bi,
                            const float* __restrict__ bg, const float* __restrict__ bo) {
    int idx = blockIdx.x * blockDim.x + threadIdx.x;
    if (idx < 512 * 1024) {
        int k = idx >> 10, j = idx & 1023;
        size_t base = ((size_t)(k >> 1) * 4096) * 2 + (k & 1);
        d_Wxh[base + (size_t)(j) * 2]        = __float2half_rn(Wf[idx]);
        d_Wxh[base + (size_t)(j + 1024) * 2] = __float2half_rn(Wi[idx]);
        d_Wxh[base + (size_t)(j + 2048) * 2] = __float2half_rn(Wg[idx]);
        d_Wxh[base + (size_t)(j + 3072) * 2] = __float2half_rn(Wo[idx]);
    }
    if (idx < 1024) {
        d_bx[idx]        = bf[idx];
        d_bx[idx + 1024] = bi[idx];
        d_bx[idx + 2048] = bg[idx];
        d_bx[idx + 3072] = bo[idx];
    }
}

// ------------------------------------------------------------------
// Pack fp16 W_fc (k-pair interleaved, N=512)
// ------------------------------------------------------------------
__global__ void packfc_kernel(const float* __restrict__ Wfc) {
    int idx = blockIdx.x * blockDim.x + threadIdx.x;   // 0 .. 524287
    int k = idx >> 9, j = idx & 511;
    d_Wfch[(((size_t)(k >> 1) * 512) + j) * 2 + (k & 1)] = __float2half_rn(Wfc[idx]);
}

// ------------------------------------------------------------------
// Generic fp16 GEMM: C[M,N] = A[M,K] @ B[K,N] + bias[N]
// A row-major fp16, B k-pair interleaved fp16, C fp32.
// 128x128x32 tiles, 8 warps (warp 64x32). M%128==0, N%128==0, K%32==0.
// ------------------------------------------------------------------
__global__ void __launch_bounds__(256) gemm_f16_bias(
    const __half* __restrict__ A, const __half* __restrict__ Bp,
    const float* __restrict__ bias, float* __restrict__ C,
    int M, int N, int K) {
    __shared__ __half sAh[128 * 40];   // 128 rows x 32 halves (+8 pad)
    __shared__ __half sBh[16 * 272];   // 16 k2-rows x 128 cols x 2 (+16 pad)

    const int tid = threadIdx.x;
    const int w = tid >> 5, lane = tid & 31;
    const int g = lane >> 2, tig = lane & 3;
    const int wm = (w >> 2) * 64, wn = (w & 3) * 32;
    const int m0 = blockIdx.y * 128, n0 = blockIdx.x * 128;

    float Cr[4][4][4];
#pragma unroll
    for (int a = 0; a < 4; a++)
#pragma unroll
        for (int b = 0; b < 4; b++)
#pragma unroll
            for (int c = 0; c < 4; c++) Cr[a][b][c] = 0.f;

    const int nk = K / 32;
    for (int kc = 0; kc < nk; kc++) {
        const int k0 = kc * 32;
        __syncthreads();
        // A slab: 128 rows x 32 halves = 512 x 16B
#pragma unroll
        for (int i = 0; i < 2; i++) {
            int lin = tid + i * 256;
            int r = lin >> 2, q = lin & 3;
            *(uint4*)(sAh + r * 40 + q * 8) =
                *(const uint4*)(A + (size_t)(m0 + r) * K + k0 + q * 8);
        }
        // B slab: 16 k2-rows x 128 cols x 2 halves = 512 x 16B
#pragma unroll
        for (int i = 0; i < 2; i++) {
            int lin = tid + i * 256;
            int k2r = lin >> 5, c4 = lin & 31;
            *(uint4*)(sBh + k2r * 272 + c4 * 8) =
                *(const uint4*)(Bp + ((size_t)((k0 >> 1) + k2r) * N + n0 + c4 * 4) * 2);
        }
        __syncthreads();

#pragma unroll
        for (int kt = 0; kt < 2; kt++) {
            unsigned bf_[4][2];
#pragma unroll
            for (int nt = 0; nt < 4; nt++) {
                int jc = wn + nt * 8 + g;
                bf_[nt][0] = *(const unsigned*)(sBh + (kt * 8 + tig) * 272 + jc * 2);
                bf_[nt][1] = *(const unsigned*)(sBh + (kt * 8 + tig + 4) * 272 + jc * 2);
            }
#pragma unroll
            for (int mt = 0; mt < 4; mt++) {
                int ro = (wm + mt * 16 + g) * 40 + kt * 16 + 2 * tig;
                unsigned a0 = *(const unsigned*)(sAh + ro);
                unsigned a1 = *(const unsigned*)(sAh + ro + 8 * 40);
                unsigned a2 = *(const unsigned*)(sAh + ro + 8);
                unsigned a3 = *(const unsigned*)(sAh + ro + 8 * 40 + 8);
#pragma unroll
                for (int nt = 0; nt < 4; nt++)
                    mma_f16(Cr[mt][nt], a0, a1, a2, a3, bf_[nt][0], bf_[nt][1]);
            }
        }
    }

    // Epilogue: bias + store fp32
#pragma unroll
    for (int mt = 0; mt < 4; mt++) {
#pragma unroll
        for (int nt = 0; nt < 4; nt++) {
            int row = m0 + wm + mt * 16 + g;
            int col = n0 + wn + nt * 8 + 2 * tig;
            float bx = bias[col], by = bias[col + 1];
            float2 v0 = make_float2(Cr[mt][nt][0] + bx, Cr[mt][nt][1] + by);
            float2 v1 = make_float2(Cr[mt][nt][2] + bx, Cr[mt][nt][3] + by);
            *(float2*)(C + (size_t)row * N + col) = v0;
            *(float2*)(C + (size_t)(row + 8) * N + col) = v1;
        }
    }
}

// ------------------------------------------------------------------
// Persistent recurrent kernel — exact R5 configuration (best measured:
// 1.72 ms). 128 blocks x 512 threads (16 warps). Block bk owns hidden
// units [bk*8, bk*8+8) x 4 gates. Warp w owns K-slice [w*64, w*64+64).
// Weights as fp16 B-fragments in regs (Wr[4][4][2] = 32 regs).
// h fp16 [t][b][k_perm]; 8 front-batched LDG.128 per warp per step.
// Single-stage reduction into 16 smem regions (gate-contiguous).
// Fence-free acq_rel grid barrier. Only change vs R5: d_H2 now fp16.
// ------------------------------------------------------------------
__global__ void __launch_bounds__(512) lstm_rec(
    const float* __restrict__ Wf, const float* __restrict__ Wi,
    const float* __restrict__ Wg, const float* __restrict__ Wo) {
    extern __shared__ float sPart[];   // 16 regions x 32 rows x 36 floats

    const int tid = threadIdx.x;
    const int w = tid >> 5, lane = tid & 31;
    const int g = lane >> 2, tig = lane & 3;
    const int kw = w * 64;
    const int bk = blockIdx.x;

    // ---- Preload weights as fp16x2 B-fragments (true k order) ----
    const float* Wp[4] = {Wf, Wi, Wg, Wo};
    unsigned Wr[4][4][2];
#pragma unroll
    for (int kt = 0; kt < 4; kt++) {
#pragma unroll
        for (int nt = 0; nt < 4; nt++) {
            const float* ws = Wp[nt] + (size_t)(512 + kw + kt * 16 + 2 * tig) * 1024 + bk * 8 + g;
            __half2 lo = __floats2half2_rn(__ldg(ws), __ldg(ws + 1024));
            __half2 hi = __floats2half2_rn(__ldg(ws + 8 * 1024), __ldg(ws + 9 * 1024));
            Wr[kt][nt][0] = *(unsigned*)&lo;
            Wr[kt][nt][1] = *(unsigned*)&hi;
        }
    }

    // State-thread mapping (first 256 threads): b = tid/8, uu = tid%8
    const int b_ = (tid >> 3) & 31, uu = tid & 7;
    const bool is_state = tid < 256;
    float creg = 0.f;
    const int j = bk * 8 + uu;
    const int ppos = perm32(j);

    // Incremented pointers
    const __half* hrd = d_Hts + kw + tig * 8;                           // += 32768
    __half* hwr = d_Hts + 32768 + (size_t)b_ * 1024 + ppos;             // += 32768
    const float* gxp = d_Gx + (size_t)(b_ * 512) * 4096 + bk * 8 + uu;  // += 4096
    __half* h2p = d_H2h + (size_t)(b_ * 512) * 1024 + bk * 8 + uu;      // += 1024
    unsigned* cntp = d_cnt;                                              // += 1

    for (int t = 0; t < 512; t++) {
        // Prefetch this step's input-projection gate values
        float gx0 = 0.f, gx1 = 0.f, gx2 = 0.f, gx3 = 0.f;
        if (is_state) {
            gx0 = __ldcs(gxp);
            gx1 = __ldcs(gxp + 1024);
            gx2 = __ldcs(gxp + 2048);
            gx3 = __ldcs(gxp + 3072);
        }

        // ---- Front-batched h loads: 8 x LDG.128 (max MLP) ----
        uint4 V[2][2][2];   // [kb][mt][row g / g+8]
#pragma unroll
        for (int kb = 0; kb < 2; kb++)
#pragma unroll
            for (int mt = 0; mt < 2; mt++) {
                V[kb][mt][0] = __ldcg((const uint4*)(hrd + kb * 32 + (mt * 16 + g) * 1024));
                V[kb][mt][1] = __ldcg((const uint4*)(hrd + kb * 32 + (mt * 16 + g + 8) * 1024));
            }

        // ---- h_t @ Wh_slice (fp16 HMMA, fp32 accum) ----
        float Cr[2][4][4];
#pragma unroll
        for (int mt = 0; mt < 2; mt++)
#pragma unroll
            for (int nt = 0; nt < 4; nt++)
#pragma unroll
                for (int c = 0; c < 4; c++) Cr[mt][nt][c] = 0.f;

#pragma unroll
        for (int kb = 0; kb < 2; kb++) {
#pragma unroll
            for (int mt = 0; mt < 2; mt++) {
                const uint4& v0 = V[kb][mt][0];
                const uint4& v1 = V[kb][mt][1];
#pragma unroll
                for (int nt = 0; nt < 4; nt++)
                    mma_f16(Cr[mt][nt], v0.x, v1.x, v0.y, v1.y,
                            Wr[2 * kb][nt][0], Wr[2 * kb][nt][1]);
#pragma unroll
                for (int nt = 0; nt < 4; nt++)
                    mma_f16(Cr[mt][nt], v0.z, v1.z, v0.w, v1.w,
                            Wr[2 * kb + 1][nt][0], Wr[2 * kb + 1][nt][1]);
            }
        }

        // ---- Write partials: region w, gate-contiguous layout ----
        {
            float* sp = sPart + w * 1152;
#pragma unroll
            for (int mt = 0; mt < 2; mt++) {
#pragma unroll
                for (int nt = 0; nt < 4; nt++) {
                    int row = mt * 16 + g, c = 2 * tig;
                    sp[row * 36 + c * 4 + nt]             = Cr[mt][nt][0];
                    sp[row * 36 + (c + 1) * 4 + nt]       = Cr[mt][nt][1];
                    sp[(row + 8) * 36 + c * 4 + nt]       = Cr[mt][nt][2];
                    sp[(row + 8) * 36 + (c + 1) * 4 + nt] = Cr[mt][nt][3];
                }
            }
        }
        __syncthreads();

        // ---- Final reduce (16 x LDS.128) + gates + state update ----
        if (is_state) {
            const float4* rp = (const float4*)sPart + (b_ * 9 + uu);
            float4 s0 = rp[0], s1 = rp[288];
#pragma unroll
            for (int r = 2; r < 16; r += 2) {
                float4 a = rp[r * 288], b = rp[(r + 1) * 288];
                s0.x += a.x; s0.y += a.y; s0.z += a.z; s0.w += a.w;
                s1.x += b.x; s1.y += b.y; s1.z += b.z; s1.w += b.w;
            }
            float F = s0.x + s1.x + gx0;
            float I = s0.y + s1.y + gx1;
            float G = s0.z + s1.z + gx2;
            float O = s0.w + s1.w + gx3;
            creg = sigm(F) * creg + sigm(I) * tanhf(G);
            float h = sigm(O) * tanhf(creg);

            __half hh = __float2half_rn(h);
            *hwr = hh;
            *h2p = hh;
        }
        __syncthreads();   // h stores + sPart reads complete

        // ---- Fence-free grid barrier (acq_rel atomic + acquire poll) ----
        if (tid == 0) {
            unsigned ret;
            asm volatile("atom.acq_rel.gpu.add.u32 %0, [%1], %2;"
                         : "=r"(ret) : "l"(cntp), "r"(1u) : "memory");
            if (ret + 1u < NB2) {
                unsigned v;
                do {
                    asm volatile("ld.acquire.gpu.u32 %0, [%1];"
                                 : "=r"(v) : "l"(cntp) : "memory");
                } while (v < NB2);
            }
        }
        __syncthreads();

        hrd += 32768; hwr += 32768; gxp += 4096; h2p += 1024; cntp += 1;
    }
}

// ------------------------------------------------------------------
// Launch sequence (graph-capturable: kernel launches only)
// ------------------------------------------------------------------
extern "C" void kernel_launch(void* const* d_in, const int* in_sizes, int n_in,
                              void* d_out, int out_size) {
    const float* x    = (const float*)d_in[0];
    const float* W_f  = (const float*)d_in[1];
    const float* b_f  = (const float*)d_in[2];
    const float* W_i  = (const float*)d_in[3];
    const float* b_i  = (const float*)d_in[4];
    const float* W_g  = (const float*)d_in[5];
    const float* b_g  = (const float*)d_in[6];
    const float* W_o  = (const float*)d_in[7];
    const float* b_o  = (const float*)d_in[8];
    const float* W_fc = (const float*)d_in[9];
    const float* b_fc = (const float*)d_in[10];
    float* out = (float*)d_out;

    void *pGx, *pH2h, *pXh, *pWxh, *pWfch, *pbx;
    cudaGetSymbolAddress(&pGx, d_Gx);
    cudaGetSymbolAddress(&pH2h, d_H2h);
    cudaGetSymbolAddress(&pXh, d_xh);
    cudaGetSymbolAddress(&pWxh, d_Wxh);
    cudaGetSymbolAddress(&pWfch, d_Wfch);
    cudaGetSymbolAddress(&pbx, d_bx);

    static bool attr_set = false;
    if (!attr_set) {
        cudaFuncSetAttribute(lstm_rec, cudaFuncAttributeMaxDynamicSharedMemorySize,
                             16 * 1152 * 4);
        attr_set = true;
    }

    init_kernel<<<128, 256>>>();
    xconv_kernel<<<16384, 256>>>(x);
    pack_kernel<<<2048, 256>>>(W_f, W_i, W_g, W_o, b_f, b_i, b_g, b_o);
    packfc_kernel<<<2048, 256>>>(W_fc);

    // Phase 1: Gx = x @ Wx + bx   (fp16 HMMA, M=16384, N=4096, K=512)
    gemm_f16_bias<<<dim3(32, 128), 256>>>(
        (const __half*)pXh, (const __half*)pWxh, (const float*)pbx,
        (float*)pGx, 16384, 4096, 512);

    // Phase 2: recurrence (persistent, 128 blocks — best measured)
    lstm_rec<<<NB2, 512, 16 * 1152 * 4>>>(W_f, W_i, W_g, W_o);

    // Phase 3: out = H2h @ W_fc + b_fc   (fp16 HMMA, M=16384, N=512, K=1024)
    gemm_f16_bias<<<dim3(4, 128), 256>>>(
        (const __half*)pH2h, (const __half*)pWfch, b_fc,
        out, 16384, 512, 1024);
}